// round 13
// baseline (speedup 1.0000x reference)
#include <cuda_runtime.h>

// x <- gelu(x + depthwise_conv3d_3x3x3(x)) x8.  [4,32,64,64,64] fp32.
// Fused 8-step cluster kernel; 128 threads; 2 output rows/thread;
// 2 planes per barrier window; cp.async; centers captured in registers.

#define CC    32
#define VOL   (64*64*64)
#define RS    72                 // words per slab row
#define RSB   (RS*4)             // 288 bytes per row
#define BUFB  8192               // bytes per plane buffer (5184 used, padded)
#define PBB   (2*BUFB)           // bytes per plane-PAIR buffer (16384)

typedef unsigned long long u64;
typedef unsigned int u32;

__device__ float  g_sA[4 * CC * VOL];
__device__ float  g_sB[4 * CC * VOL];
__device__ __align__(16) float4 g_zero4 = {0.f, 0.f, 0.f, 0.f};

// ---------- packed f32x2 helpers ----------
__device__ __forceinline__ u64 pack2(float lo, float hi) {
    u64 r; asm("mov.b64 %0, {%1, %2};" : "=l"(r) : "f"(lo), "f"(hi)); return r;
}
__device__ __forceinline__ void unpack2(u64 v, float& lo, float& hi) {
    asm("mov.b64 {%0, %1}, %2;" : "=f"(lo), "=f"(hi) : "l"(v));
}
__device__ __forceinline__ void fma2(u64& acc, u64 a, u64 b) {
    asm("fma.rn.f32x2 %0, %1, %2, %0;" : "+l"(acc) : "l"(a), "l"(b));
}
__device__ __forceinline__ void mul2(u64& d, u64 a, u64 b) {
    asm("mul.rn.f32x2 %0, %1, %2;" : "=l"(d) : "l"(a), "l"(b));
}
__device__ __forceinline__ u64 add2(u64 a, u64 b) {
    u64 r; asm("add.rn.f32x2 %0, %1, %2;" : "=l"(r) : "l"(a), "l"(b)); return r;
}

// ---------- volatile SMEM loads (addresses repeat every 2 windows) ----------
#define LDSP(x, y, base, IMM)                                            \
    asm volatile("ld.shared.v2.u64 {%0, %1}, [%2+%3];"                   \
                 : "=l"(x), "=l"(y) : "r"(base), "n"(IMM))

// ---------- cp.async ----------
#define CPA16(dst, src)                                                  \
    asm volatile("cp.async.cg.shared.global [%0], [%1], 16;"             \
                 :: "r"(dst), "l"(src))
#define CPA16P(pred, dst, src)                                           \
    asm volatile("{ .reg .pred p; setp.ne.s32 p, %0, 0;"                 \
                 "  @p cp.async.cg.shared.global [%1], [%2], 16; }"      \
                 :: "r"(pred), "r"(dst), "l"(src))
#define CPCOMMIT() asm volatile("cp.async.commit_group;")
#define CPWAIT0()  asm volatile("cp.async.wait_group 0;")

// Exact-erf GELU via A&S 7.1.26 (abs err ~1.5e-7, tol 1e-3).
__device__ __forceinline__ float gelu_exact(float x) {
    float z = x * 0.70710678118654752440f;
    float a = fabsf(z);
    float d = fmaf(0.3275911f, a, 1.0f);
    float t; asm("rcp.approx.f32 %0, %1;" : "=f"(t) : "f"(d));
    float p = fmaf(t, 1.061405429f, -1.453152027f);
    p = fmaf(t, p, 1.421413741f);
    p = fmaf(t, p, -0.284496736f);
    p = fmaf(t, p, 0.254829592f);
    p = p * t;
    float e; asm("ex2.approx.f32 %0, %1;" : "=f"(e) : "f"(-a * a * 1.4426950408889634f));
    float er = fmaf(-p, e, 1.0f);
    er = copysignf(er, z);
    return 0.5f * fmaf(x, er, x);
}

// Load one input row's 5 stencil windows as u64 pairs: 3 conflict-free
// LDS.128 from base rCur + immediate, ALU assembly of the cross pairs.
#define LOADQ(OFF)                                                       \
    u64 E0, E1, Q1, Q3, F0, F1;                                          \
    LDSP(E0, E1, rCur, (OFF));                                           \
    LDSP(Q1, Q3, rCur, (OFF) + 16);                                      \
    LDSP(F0, F1, rCur, (OFF) + 32);                                      \
    float fm, fp, f0, f1, f2, f3, dm0, dm1;                              \
    unpack2(E1, dm0, fm);                                                \
    unpack2(F0, fp, dm1);                                                \
    unpack2(Q1, f0, f1);                                                 \
    unpack2(Q3, f2, f3);                                                 \
    u64 Q0 = pack2(fm, f0), Q2 = pack2(f1, f2), Q4 = pack2(f3, fp);      \
    (void)E0; (void)F1; (void)dm0; (void)dm1;

#define FMA6(S0, S1, WB)                                                 \
    fma2(S0, W2[(WB)+0], Q0); fma2(S1, W2[(WB)+0], Q2);                  \
    fma2(S0, W2[(WB)+1], Q1); fma2(S1, W2[(WB)+1], Q3);                  \
    fma2(S0, W2[(WB)+2], Q2); fma2(S1, W2[(WB)+2], Q4);
#define MUL6(S0, S1, WB)                                                 \
    mul2(S0, W2[(WB)+0], Q0); mul2(S1, W2[(WB)+0], Q2);                  \
    fma2(S0, W2[(WB)+1], Q1); fma2(S1, W2[(WB)+1], Q3);                  \
    fma2(S0, W2[(WB)+2], Q2); fma2(S1, W2[(WB)+2], Q4);

// NOTE: locals use reserved names _t0/_t1 — NEVER reuse accumulator names
// here (round-12 bug: `u64 u0 = add2(u0,...)` self-bound the NEW u0).
#define STORE4(A0, A1, C0, C1, PTR)                                      \
    {                                                                    \
        u64 _t0 = add2(A0, C0), _t1 = add2(A1, C1);                      \
        float _o0, _o1, _o2, _o3;                                        \
        unpack2(_t0, _o0, _o1); unpack2(_t1, _o2, _o3);                  \
        float4 _ov = make_float4(gelu_exact(_o0), gelu_exact(_o1),       \
                                 gelu_exact(_o2), gelu_exact(_o3));      \
        *(float4*)(PTR) = _ov;                                           \
    }

// One plane (byte offset POFF over rCur): 4 rows; X completes (kz2),
// Y mid (kz1), Z fresh (kz0, MUL at first touch). Captures row centers
// (Q1,Q3 at r=1,2) = this plane's residual centers into C quad.
#define PLANE(POFF, X0,X1,X2,X3, Y0,Y1,Y2,Y3, Z0,Z1,Z2,Z3, C0,C1,C2,C3) \
    { LOADQ((POFF))           FMA6(X0,X1,18) FMA6(Y0,Y1,9)  MUL6(Z0,Z1,0) } \
    { LOADQ((POFF) + RSB)     C0 = Q1; C1 = Q3;                           \
                              FMA6(X0,X1,21) FMA6(Y0,Y1,12) FMA6(Z0,Z1,3) \
                              FMA6(X2,X3,18) FMA6(Y2,Y3,9)  MUL6(Z2,Z3,0) } \
    { LOADQ((POFF) + 2*RSB)   C2 = Q1; C3 = Q3;                           \
                              FMA6(X0,X1,24) FMA6(Y0,Y1,15) FMA6(Z0,Z1,6) \
                              FMA6(X2,X3,21) FMA6(Y2,Y3,12) FMA6(Z2,Z3,3) } \
    { LOADQ((POFF) + 3*RSB)   FMA6(X2,X3,24) FMA6(Y2,Y3,15) FMA6(Z2,Z3,6) }

// Window k (planes 2k, 2k+1 in current pair buffer at rCur):
// wait pair k, barrier, prefetch pair k+1 into the other pair buffer,
// plane A (U completes -> store out(2k-1) w/ carried centers),
// plane B (V completes -> store out(2k) w/ centers captured at plane A;
// U recycled fresh; plane B centers -> carry cenC for next window).
#define WINDOW2(U0,U1,U2,U3, V0,V1,V2,V3, W0,W1,W2q,W3, DOST0, DOPF)     \
    do {                                                                 \
        CPWAIT0();                                                       \
        __syncthreads();                                                 \
        if (DOPF) {                                                      \
            CPA16(dc0 + tog, p0);        CPA16(dc0 + tog + BUFB, p0 + st0); \
            CPA16(dc1 + tog, p1);        CPA16(dc1 + tog + BUFB, p1 + st1); \
            CPA16P(isB, dc2 + tog, p2);  CPA16P(isB, dc2 + tog + BUFB, p2 + st2); \
            CPCOMMIT();                                                  \
            p0 += 2 * st0; p1 += 2 * st1; p2 += 2 * st2;                 \
        }                                                                \
        u64 cv0, cv1, cv2, cv3;                                          \
        PLANE(0,    U0,U1,U2,U3, V0,V1,V2,V3, W0,W1,W2q,W3, cv0,cv1,cv2,cv3) \
        if (DOST0) {                                                     \
            STORE4(U0, U1, cenC0, cenC1, optr);                          \
            STORE4(U2, U3, cenC2, cenC3, optr + 64);                     \
        }                                                                \
        PLANE(BUFB, V0,V1,V2,V3, W0,W1,W2q,W3, U0,U1,U2,U3,              \
              cenC0,cenC1,cenC2,cenC3)                                   \
        STORE4(V0, V1, cv0, cv1, optr + 4096);                           \
        STORE4(V2, V3, cv2, cv3, optr + 4096 + 64);                      \
        optr += 8192;                                                    \
        rCur += tog; dc0 += tog; dc1 += tog; dc2 += tog; tog = -tog;     \
    } while (0)

// Cluster of 4 = the 4 H-chunks of one (b,c); halos only cross H-chunks.
__global__ void __launch_bounds__(128, 4) __cluster_dims__(4, 1, 1)
fused_kernel(const float* __restrict__ x, float* __restrict__ outF,
             const float* __restrict__ wts,
             float* __restrict__ sA, float* __restrict__ sB)
{
    const int tid = threadIdx.x;             // 0..127
    const int tx  = tid & 15;                // w quad
    const int ty  = tid >> 4;                // 0..7: output rows 2ty, 2ty+1
    const int h0  = blockIdx.x * 16;
    const int c   = blockIdx.y;
    const int b   = blockIdx.z;
    const size_t volOff = (size_t)(b * CC + c) * VOL;

    u64 W2[27];
#pragma unroll
    for (int i = 0; i < 27; ++i) {
        float w = __ldg(&wts[c * 27 + i]);
        W2[i] = pack2(w, w);
    }

    // 4 plane buffers (2 pairs), each 2048 words (row: word3=left halo 0,
    // 4..67 data, 68=right halo 0).
    __shared__ __align__(16) float sl[4 * 2048];

    for (int i = tid; i < 144; i += 128) {   // zero halo words of all 4 buffers
        int buf = i / 36, k = i % 36;
        sl[buf * 2048 + (k % 18) * RS + (k < 18 ? 3 : 68)] = 0.f;
    }

    const u32 sbase = (u32)__cvta_generic_to_shared(sl);
    const u32 rB    = sbase + ty * 2 * RSB + 16 * tx;

    // Loader: thread covers 16B chunks of slab rows lr, lr+8, (tid<32: lr+16).
    const int lr = tid >> 4, lq = tid & 15;
    const int gh0 = h0 - 1 + lr;
    const int gh1 = gh0 + 8;
    const int gh2 = gh0 + 16;
    const bool v0 = (gh0 >= 0) && (gh0 < 64);
    const bool v1 = (gh1 < 64);
    const bool v2 = (tid < 32) && (gh2 < 64);
    const int isB = (tid < 32) ? 1 : 0;
    const int of0 = gh0 * 16 + lq, of1 = gh1 * 16 + lq, of2 = gh2 * 16 + lq;
    const int st0 = v0 ? 1024 : 0, st1 = v1 ? 1024 : 0, st2 = v2 ? 1024 : 0;

    const u32 d0 = sbase + (lr * RS + 4 + 4 * lq) * 4;
    const u32 d1 = d0 + 8 * RSB;
    const u32 d2 = d0 + 16 * RSB;

    const int outOfs = (h0 + 2 * ty) * 64 + 4 * tx;

    const float* sin = x;

#pragma unroll 1
    for (int s = 0; s < 8; ++s) {
        float* sout = (s == 7) ? outF : ((s & 1) ? sB : sA);
        const float* vin = sin + volOff;

        const float4* p0 = v0 ? (const float4*)vin + of0 : &g_zero4;
        const float4* p1 = v1 ? (const float4*)vin + of1 : &g_zero4;
        const float4* p2 = v2 ? (const float4*)vin + of2 : &g_zero4;
        float* optr = (sout + volOff) + outOfs - 4096;

        // Prologue: pair 0 (planes 0,1) -> pair buffer 0.
        CPA16(d0, p0);       CPA16(d0 + BUFB, p0 + st0);
        CPA16(d1, p1);       CPA16(d1 + BUFB, p1 + st1);
        CPA16P(isB, d2, p2); CPA16P(isB, d2 + BUFB, p2 + st2);
        CPCOMMIT();
        p0 += 2 * st0; p1 += 2 * st1; p2 += 2 * st2;

        u32 rCur = rB, dc0 = d0, dc1 = d1, dc2 = d2;
        int tog = PBB;

        // 3 rotating accumulator quads + carried center quad.
        u64 u0=0,u1=0,u2=0,u3=0, v0q=0,v1q=0,v2q=0,v3q=0,
            w0q=0,w1q=0,w2q=0,w3q=0;
        u64 cenC0=0, cenC1=0, cenC2=0, cenC3=0;

        // Roles rotate (U,V,W) -> (W,U,V) each window; period 3.
        WINDOW2(u0,u1,u2,u3, v0q,v1q,v2q,v3q, w0q,w1q,w2q,w3q, false, true); // w0
#pragma unroll 1
        for (int i = 0; i < 10; ++i) {                                       // w1..w30
            WINDOW2(w0q,w1q,w2q,w3q, u0,u1,u2,u3, v0q,v1q,v2q,v3q, true, true);
            WINDOW2(v0q,v1q,v2q,v3q, w0q,w1q,w2q,w3q, u0,u1,u2,u3, true, true);
            WINDOW2(u0,u1,u2,u3, v0q,v1q,v2q,v3q, w0q,w1q,w2q,w3q, true, true);
        }
        WINDOW2(w0q,w1q,w2q,w3q, u0,u1,u2,u3, v0q,v1q,v2q,v3q, true, false);  // w31

        // out(63): kz2 (plane 64) = 0; partial = W-slot of w31 = v quad;
        // centers = plane 63's, carried in cenC.
        STORE4(v0q, v1q, cenC0, cenC1, optr);
        STORE4(v2q, v3q, cenC2, cenC3, optr + 64);

        if (s < 7) {
            __threadfence();
            asm volatile("barrier.cluster.arrive.aligned;" ::: "memory");
            asm volatile("barrier.cluster.wait.aligned;"   ::: "memory");
        }
        sin = sout;
    }
}

extern "C" void kernel_launch(void* const* d_in, const int* in_sizes, int n_in,
                              void* d_out, int out_size)
{
    const float* x = (const float*)d_in[0];
    const float* w = (const float*)d_in[1];
    float* out = (float*)d_out;

    float *sA = nullptr, *sB = nullptr;
    cudaGetSymbolAddress((void**)&sA, g_sA);
    cudaGetSymbolAddress((void**)&sB, g_sB);

    dim3 grid(4, CC, 4);    // x-dim (H-chunks) grouped into clusters of 4
    dim3 blk(128);
    fused_kernel<<<grid, blk>>>(x, out, w, sA, sB);
}

// round 14
// speedup vs baseline: 1.0415x; 1.0415x over previous
#include <cuda_runtime.h>

// x <- gelu(x + depthwise_conv3d_3x3x3(x)) x8.  [4,32,64,64,64] fp32.
// Fused 8-step cluster kernel; 128 threads; 2 output H-rows per thread;
// cp.async loader; single-copy slabs; 3 rotating plane buffers.
// (r10 base + A&S 7.1.27 GELU (1 MUFU) + narrowed edge LDS.)

#define CC    32
#define VOL   (64*64*64)
#define RS    72                 // words per slab row
#define RSB   (RS*4)             // 288 bytes per row
#define BUFB  (18*RSB)           // 5184 bytes per plane buffer

typedef unsigned long long u64;
typedef unsigned int u32;

__device__ float  g_sA[4 * CC * VOL];
__device__ float  g_sB[4 * CC * VOL];
__device__ __align__(16) float4 g_zero4 = {0.f, 0.f, 0.f, 0.f};

// ---------- packed f32x2 helpers ----------
__device__ __forceinline__ u64 pack2(float lo, float hi) {
    u64 r; asm("mov.b64 %0, {%1, %2};" : "=l"(r) : "f"(lo), "f"(hi)); return r;
}
__device__ __forceinline__ void unpack2(u64 v, float& lo, float& hi) {
    asm("mov.b64 {%0, %1}, %2;" : "=f"(lo), "=f"(hi) : "l"(v));
}
__device__ __forceinline__ void fma2(u64& acc, u64 a, u64 b) {
    asm("fma.rn.f32x2 %0, %1, %2, %0;" : "+l"(acc) : "l"(a), "l"(b));
}
__device__ __forceinline__ void mul2(u64& d, u64 a, u64 b) {
    asm("mul.rn.f32x2 %0, %1, %2;" : "=l"(d) : "l"(a), "l"(b));
}
__device__ __forceinline__ u64 add2(u64 a, u64 b) {
    u64 r; asm("add.rn.f32x2 %0, %1, %2;" : "=l"(r) : "l"(a), "l"(b)); return r;
}

// ---------- volatile SMEM loads (no CSE across planes / no hoist over bars) ----------
#define LDSP(x, y, base, IMM)                                            \
    asm volatile("ld.shared.v2.u64 {%0, %1}, [%2+%3];"                   \
                 : "=l"(x), "=l"(y) : "r"(base), "n"(IMM))
#define LDS1(x, base, IMM)                                               \
    asm volatile("ld.shared.u64 %0, [%1+%2];"                            \
                 : "=l"(x) : "r"(base), "n"(IMM))

// ---------- cp.async ----------
#define CPA16(dst, src)                                                  \
    asm volatile("cp.async.cg.shared.global [%0], [%1], 16;"             \
                 :: "r"(dst), "l"(src))
#define CPA16P(pred, dst, src)                                           \
    asm volatile("{ .reg .pred p; setp.ne.s32 p, %0, 0;"                 \
                 "  @p cp.async.cg.shared.global [%1], [%2], 16; }"      \
                 :: "r"(pred), "r"(dst), "l"(src))
#define CPCOMMIT() asm volatile("cp.async.commit_group;")
#define CPWAIT0()  asm volatile("cp.async.wait_group 0;")

// Exact-erf GELU via A&S 7.1.27: erf(a) = 1 - (1 + a1 a + ... + a6 a^6)^-16,
// max abs err 3e-7 (tol 1e-3). One MUFU (rcp) instead of rcp+ex2; the Horner
// chain is FFMA-imm (rt=1).
__device__ __forceinline__ float gelu16(float x) {
    float a = fabsf(x) * 0.70710678118654752440f;    // |z|, abs folds into FMUL
    float p = fmaf(0.0000430638f, a, 0.0002765672f);
    p = fmaf(p, a, 0.0001520143f);
    p = fmaf(p, a, 0.0092705272f);
    p = fmaf(p, a, 0.0422820123f);
    p = fmaf(p, a, 0.0705230784f);
    p = fmaf(p, a, 1.0f);
    float r; asm("rcp.approx.f32 %0, %1;" : "=f"(r) : "f"(p));
    r = r * r; r = r * r; r = r * r; r = r * r;      // p^-16
    float er = 1.0f - r;                             // erf(|z|)
    er = copysignf(er, x);                           // erf(z)
    return 0.5f * fmaf(x, er, x);                    // 0.5*x*(1+erf)
}

// Load one input row's 5 stencil windows as u64 pairs: 1 LDS.64 + 1 LDS.128 +
// 1 LDS.64 (conflict-free) + ALU assembly of the cross pairs.
#define LOADQ(OFF)                                                       \
    u64 E1, Q1, Q3, F0;                                                  \
    LDS1(E1, rB, (OFF) + 8);                                             \
    LDSP(Q1, Q3, rB, (OFF) + 16);                                        \
    LDS1(F0, rB, (OFF) + 32);                                            \
    float fm, fp, f0, f1, f2, f3, dm0, dm1;                              \
    unpack2(E1, dm0, fm);                                                \
    unpack2(F0, fp, dm1);                                                \
    unpack2(Q1, f0, f1);                                                 \
    unpack2(Q3, f2, f3);                                                 \
    u64 Q0 = pack2(fm, f0), Q2 = pack2(f1, f2), Q4 = pack2(f3, fp);      \
    (void)dm0; (void)dm1;

#define FMA6(S0, S1, WB)                                                 \
    fma2(S0, W2[(WB)+0], Q0); fma2(S1, W2[(WB)+0], Q2);                  \
    fma2(S0, W2[(WB)+1], Q1); fma2(S1, W2[(WB)+1], Q3);                  \
    fma2(S0, W2[(WB)+2], Q2); fma2(S1, W2[(WB)+2], Q4);
#define MUL6(S0, S1, WB)                                                 \
    mul2(S0, W2[(WB)+0], Q0); mul2(S1, W2[(WB)+0], Q2);                  \
    fma2(S0, W2[(WB)+1], Q1); fma2(S1, W2[(WB)+1], Q3);                  \
    fma2(S0, W2[(WB)+2], Q2); fma2(S1, W2[(WB)+2], Q4);

// Locals use reserved _names (macro-capture bug class, round 12).
#define STORE4(A0, A1, C0, C1, PTR)                                      \
    {                                                                    \
        u64 _t0 = add2(A0, C0), _t1 = add2(A1, C1);                      \
        float _o0, _o1, _o2, _o3;                                        \
        unpack2(_t0, _o0, _o1); unpack2(_t1, _o2, _o3);                  \
        float4 _ov = make_float4(gelu16(_o0), gelu16(_o1),               \
                                 gelu16(_o2), gelu16(_o3));              \
        *(float4*)(PTR) = _ov;                                           \
    }

// Window p: wait plane p's cp.async, barrier, issue cp.async p+1 (disjoint buf),
// compute 4 input rows (2 output rows x 3 pipeline stages), store out(p-1).
// X completes out(p-1) [kz2], Y = out(p) [kz1], Z = out(p+1) fresh [kz0].
#define WINDOW(SB, SBN, SBC, X0,X1,X2,X3, Y0,Y1,Y2,Y3, Z0,Z1,Z2,Z3, DOST, DOPF) \
    do {                                                                 \
        CPWAIT0();                                                       \
        __syncthreads();                                                 \
        if (DOPF) {                                                      \
            CPA16(d0 + (SBN), p0); CPA16(d1 + (SBN), p1);                \
            CPA16P(isB, d2 + (SBN), p2);                                 \
            CPCOMMIT();                                                  \
            p0 += st0; p1 += st1; p2 += st2;                             \
        }                                                                \
        u64 c0, c1, c2, c3;                                              \
        if (DOST) {                                                      \
            LDSP(c0, c1, rB, (SBC) + RSB + 16);                          \
            LDSP(c2, c3, rB, (SBC) + 2 * RSB + 16);                      \
        }                                                                \
        { LOADQ((SB))           MUL6(Z0,Z1,0)  FMA6(Y0,Y1,9)   FMA6(X0,X1,18) }  \
        { LOADQ((SB) + RSB)     FMA6(Z0,Z1,3)  FMA6(Y0,Y1,12)  FMA6(X0,X1,21)    \
                                MUL6(Z2,Z3,0)  FMA6(Y2,Y3,9)   FMA6(X2,X3,18) }  \
        { LOADQ((SB) + 2*RSB)   FMA6(Z0,Z1,6)  FMA6(Y0,Y1,15)  FMA6(X0,X1,24)    \
                                FMA6(Z2,Z3,3)  FMA6(Y2,Y3,12)  FMA6(X2,X3,21) }  \
        { LOADQ((SB) + 3*RSB)   FMA6(Z2,Z3,6)  FMA6(Y2,Y3,15)  FMA6(X2,X3,24) }  \
        if (DOST) {                                                      \
            STORE4(X0, X1, c0, c1, optr);                                \
            STORE4(X2, X3, c2, c3, optr + 64);                           \
            optr += 4096;                                                \
        }                                                                \
    } while (0)

// Cluster of 4 = the 4 H-chunks of one (b,c); halos only cross H-chunks.
__global__ void __launch_bounds__(128, 4) __cluster_dims__(4, 1, 1)
fused_kernel(const float* __restrict__ x, float* __restrict__ outF,
             const float* __restrict__ wts,
             float* __restrict__ sA, float* __restrict__ sB)
{
    const int tid = threadIdx.x;             // 0..127
    const int tx  = tid & 15;                // w quad
    const int ty  = tid >> 4;                // 0..7: output rows 2ty, 2ty+1
    const int h0  = blockIdx.x * 16;
    const int c   = blockIdx.y;
    const int b   = blockIdx.z;
    const size_t volOff = (size_t)(b * CC + c) * VOL;

    u64 W2[27];
#pragma unroll
    for (int i = 0; i < 27; ++i) {
        float w = __ldg(&wts[c * 27 + i]);
        W2[i] = pack2(w, w);
    }

    // 3 rotating plane buffers; row: words 0..2 pad, 3 = left halo(0),
    // 4..67 data, 68 = right halo(0), 69..71 pad.
    __shared__ __align__(16) float sl[3 * 18 * RS];

    if (tid < 108) {                         // zero halo words once
        int buf = tid / 36, k = tid % 36;
        sl[buf * (18 * RS) + (k % 18) * RS + (k < 18 ? 3 : 68)] = 0.f;
    }

    const u32 sbase = (u32)__cvta_generic_to_shared(sl);
    const u32 rB    = sbase + ty * 2 * RSB + 16 * tx;   // word 4tx of row 2ty

    // Loader: thread covers 16B chunks of rows lr, lr+8, (tid<32: lr+16).
    const int lr = tid >> 4, lq = tid & 15;
    const int gh0 = h0 - 1 + lr;
    const int gh1 = gh0 + 8;
    const int gh2 = gh0 + 16;
    const bool v0 = (gh0 >= 0) && (gh0 < 64);
    const bool v1 = (gh1 < 64);                         // gh1 >= 7 always
    const bool v2 = (tid < 32) && (gh2 < 64);
    const int isB = (tid < 32) ? 1 : 0;
    const int of0 = gh0 * 16 + lq, of1 = gh1 * 16 + lq, of2 = gh2 * 16 + lq;
    const int st0 = v0 ? 1024 : 0, st1 = v1 ? 1024 : 0, st2 = v2 ? 1024 : 0;

    const u32 d0 = sbase + (lr * RS + 4 + 4 * lq) * 4;
    const u32 d1 = d0 + 8 * RSB;
    const u32 d2 = d0 + 16 * RSB;

    const int outOfs = (h0 + 2 * ty) * 64 + 4 * tx;

    const float* sin = x;

#pragma unroll 1
    for (int s = 0; s < 8; ++s) {
        float* sout = (s == 7) ? outF : ((s & 1) ? sB : sA);
        const float* vin = sin + volOff;

        const float4* p0 = v0 ? (const float4*)vin + of0 : &g_zero4;
        const float4* p1 = v1 ? (const float4*)vin + of1 : &g_zero4;
        const float4* p2 = v2 ? (const float4*)vin + of2 : &g_zero4;
        float* optr = (sout + volOff) + outOfs;

        // Prologue: plane 0 -> buf0.
        CPA16(d0, p0); CPA16(d1, p1); CPA16P(isB, d2, p2);
        CPCOMMIT();
        p0 += st0; p1 += st1; p2 += st2;

        // s0..s2 role quads (out-row0 h0,h1, out-row1 h0,h1).
        u64 s00=0,s01=0,s02=0,s03=0, s10=0,s11=0,s12=0,s13=0,
            s20=0,s21=0,s22=0,s23=0;

        // Window p: X=s[(p+2)%3], Y=s[p%3], Z=s[(p+1)%3]; bufs SB=p%3 etc.
        WINDOW(0, BUFB, 2*BUFB, s20,s21,s22,s23, s00,s01,s02,s03,
               s10,s11,s12,s13, false, true);                        // p=0
#pragma unroll 1
        for (int i = 0; i < 20; ++i) {                               // p=1..60
            WINDOW(BUFB, 2*BUFB, 0, s00,s01,s02,s03, s10,s11,s12,s13,
                   s20,s21,s22,s23, true, true);                     // p%3==1
            WINDOW(2*BUFB, 0, BUFB, s10,s11,s12,s13, s20,s21,s22,s23,
                   s00,s01,s02,s03, true, true);                     // p%3==2
            WINDOW(0, BUFB, 2*BUFB, s20,s21,s22,s23, s00,s01,s02,s03,
                   s10,s11,s12,s13, true, true);                     // p%3==0
        }
        WINDOW(BUFB, 2*BUFB, 0, s00,s01,s02,s03, s10,s11,s12,s13,
               s20,s21,s22,s23, true, true);                         // p=61
        WINDOW(2*BUFB, 0, BUFB, s10,s11,s12,s13, s20,s21,s22,s23,
               s00,s01,s02,s03, true, true);                         // p=62
        WINDOW(0, BUFB, 2*BUFB, s20,s21,s22,s23, s00,s01,s02,s03,
               s10,s11,s12,s13, true, false);                        // p=63

        // out(63): kz2 (plane 64) = 0; partial = Y of window 63 = s0;
        // centers = plane 63 (buf0) rows 2ty+1, 2ty+2.
        {
            u64 c0, c1, c2, c3;
            LDSP(c0, c1, rB, RSB + 16);
            LDSP(c2, c3, rB, 2 * RSB + 16);
            STORE4(s00, s01, c0, c1, optr);
            STORE4(s02, s03, c2, c3, optr + 64);
        }

        if (s < 7) {
            __threadfence();
            asm volatile("barrier.cluster.arrive.aligned;" ::: "memory");
            asm volatile("barrier.cluster.wait.aligned;"   ::: "memory");
        }
        sin = sout;
    }
}

extern "C" void kernel_launch(void* const* d_in, const int* in_sizes, int n_in,
                              void* d_out, int out_size)
{
    const float* x = (const float*)d_in[0];
    const float* w = (const float*)d_in[1];
    float* out = (float*)d_out;

    float *sA = nullptr, *sB = nullptr;
    cudaGetSymbolAddress((void**)&sA, g_sA);
    cudaGetSymbolAddress((void**)&sB, g_sB);

    dim3 grid(4, CC, 4);    // x-dim (H-chunks) grouped into clusters of 4
    dim3 blk(128);
    fused_kernel<<<grid, blk>>>(x, out, w, sA, sB);
}